// round 3
// baseline (speedup 1.0000x reference)
#include <cuda_runtime.h>
#include <math.h>

#define HW 56
#define CDIM 128
#define WS 7
#define NTOK 49
#define NWIN_TOT 4096
#define NPIX 200704           // 64*56*56
#define QS 130                // q smem row stride (pairs: 65, odd -> conflict-free)
#define KS 134                // k smem row stride (pairs: 67, odd -> conflict-free)

typedef unsigned long long u64_t;

// ---------------- device scratch ----------------
__device__ float g_qkv[(size_t)NPIX * 384];      // 294 MB
__device__ float g_o[(size_t)NPIX * 128];        // attn@v out (window order)
__device__ float g_x1[(size_t)NPIX * 128];       // x + LN(attn)
__device__ float g_h[(size_t)NPIX * 512];        // gelu(fc1)
__device__ float g_bias16[13 * 13 * 4];
__device__ float g_scale[4];
__device__ float g_qkvbias[384];

// ---------------- packed f32x2 FMA ----------------
__device__ __forceinline__ float2 ffma2(float2 a, float2 b, float2 c) {
    u64_t au = *reinterpret_cast<u64_t*>(&a);
    u64_t bu = *reinterpret_cast<u64_t*>(&b);
    u64_t cu = *reinterpret_cast<u64_t*>(&c);
    u64_t du;
    asm("fma.rn.f32x2 %0, %1, %2, %3;" : "=l"(du) : "l"(au), "l"(bu), "l"(cu));
    return *reinterpret_cast<float2*>(&du);
}

// ---------------- K1: prep ----------------
__device__ __forceinline__ float rpb_f(float v) {
    float sv = v * (2.0f / 9.0f);
    float s = (sv > 0.f) ? 1.f : ((sv < 0.f) ? -1.f : 0.f);
    return s * log1pf(fabsf(sv)) * (1.0f / 2.0794415416798357f);
}

__global__ void k_prep(const float* __restrict__ logit_scale,
                       const float* __restrict__ rpe_w1,
                       const float* __restrict__ rpe_b1,
                       const float* __restrict__ rpe_w2,
                       const float* __restrict__ q_bias,
                       const float* __restrict__ v_bias) {
    int bid = blockIdx.x, t = threadIdx.x;
    if (bid == 169) {
        if (t < 4) g_scale[t] = expf(fminf(logit_scale[t], logf(100.0f)));
        for (int c = t; c < 384; c += 128)
            g_qkvbias[c] = (c < 128) ? q_bias[c] : (c >= 256 ? v_bias[c - 256] : 0.f);
        return;
    }
    int dy = bid / 13 - 6, dx = bid % 13 - 6;
    float t0 = rpb_f((float)dy), t1 = rpb_f((float)dx);
    float a0 = 0, a1 = 0, a2 = 0, a3 = 0;
    for (int k = t; k < 512; k += 128) {
        float hsum = fmaf(t0, rpe_w1[k], fmaf(t1, rpe_w1[512 + k], rpe_b1[k]));
        if (hsum > 0.f) {
            const float* w2r = rpe_w2 + k * 4;
            a0 = fmaf(hsum, w2r[0], a0);
            a1 = fmaf(hsum, w2r[1], a1);
            a2 = fmaf(hsum, w2r[2], a2);
            a3 = fmaf(hsum, w2r[3], a3);
        }
    }
    #pragma unroll
    for (int o = 16; o; o >>= 1) {
        a0 += __shfl_xor_sync(0xffffffffu, a0, o);
        a1 += __shfl_xor_sync(0xffffffffu, a1, o);
        a2 += __shfl_xor_sync(0xffffffffu, a2, o);
        a3 += __shfl_xor_sync(0xffffffffu, a3, o);
    }
    __shared__ float red[4][4];
    int w = t >> 5;
    if ((t & 31) == 0) { red[w][0] = a0; red[w][1] = a1; red[w][2] = a2; red[w][3] = a3; }
    __syncthreads();
    if (t < 4) {
        float s = red[0][t] + red[1][t] + red[2][t] + red[3][t];
        g_bias16[bid * 4 + t] = 16.f / (1.f + expf(-s));
    }
}

// ---------------- GEMM: BM=128, BN=128, BK=8, 256 thr, 16x4 per thread ----------------
// EPI: 0=bias ; 2=bias+gelu ; 3=proj: bias+LN+residual(scatter x)->g_x1 ;
//      4=fc2 : bias+LN+residual(x1)->out
__device__ __forceinline__ float gelu_exact(float z) {
    return 0.5f * z * (1.0f + erff(z * 0.7071067811865475f));
}

__device__ __forceinline__ float wred(float s) {
    #pragma unroll
    for (int o = 16; o; o >>= 1) s += __shfl_xor_sync(0xffffffffu, s, o);
    return s;
}

template<int K, int N, int EPI>
__global__ void __launch_bounds__(256, 2) k_gemm(
    const float* __restrict__ A, const float* __restrict__ Bm,
    const float* __restrict__ bias, float* __restrict__ out,
    const float* __restrict__ resid, const float* __restrict__ lng,
    const float* __restrict__ lnb)
{
    __shared__ __align__(16) float2 Asd[2][8][128];  // duplicated pairs {v,v}
    __shared__ __align__(16) float  Bs[2][8][128];
    int t = threadIdx.x;
    int cx = t & 31, cy = t >> 5;                    // cols cx*4.., rows cy*16..
    int bm = blockIdx.x * 128;
    int bn = blockIdx.y * 128;

    const int arow = t >> 1, akq = (t & 1) * 4;
    const int bkr = t >> 5, bcol = (t & 31) * 4;

    const float* Aptr = A + (size_t)(bm + arow) * K + akq;
    const float* Bptr = Bm + (size_t)bkr * N + bn + bcol;

    float4 ra = *(const float4*)Aptr;
    float4 rb = *(const float4*)Bptr;
    Asd[0][akq + 0][arow] = make_float2(ra.x, ra.x);
    Asd[0][akq + 1][arow] = make_float2(ra.y, ra.y);
    Asd[0][akq + 2][arow] = make_float2(ra.z, ra.z);
    Asd[0][akq + 3][arow] = make_float2(ra.w, ra.w);
    *(float4*)&Bs[0][bkr][bcol] = rb;
    __syncthreads();

    float2 acc[16][2];
    #pragma unroll
    for (int i = 0; i < 16; ++i) { acc[i][0] = make_float2(0.f, 0.f); acc[i][1] = make_float2(0.f, 0.f); }

    const int S = K / 8;
    #pragma unroll 1
    for (int s = 0; s < S; ++s) {
        if (s + 1 < S) {
            ra = *(const float4*)(Aptr + (s + 1) * 8);
            rb = *(const float4*)(Bptr + (size_t)(s + 1) * 8 * N);
        }
        int buf = s & 1;
        #pragma unroll
        for (int kk = 0; kk < 8; ++kk) {
            float4 bq = *(const float4*)&Bs[buf][kk][cx * 4];
            float2 b0 = make_float2(bq.x, bq.y);
            float2 b1 = make_float2(bq.z, bq.w);
            const float4* ap = (const float4*)&Asd[buf][kk][cy * 16];
            #pragma unroll
            for (int i2 = 0; i2 < 8; ++i2) {
                float4 av = ap[i2];
                float2 a0 = make_float2(av.x, av.y);
                float2 a1 = make_float2(av.z, av.w);
                acc[i2 * 2][0]     = ffma2(a0, b0, acc[i2 * 2][0]);
                acc[i2 * 2][1]     = ffma2(a0, b1, acc[i2 * 2][1]);
                acc[i2 * 2 + 1][0] = ffma2(a1, b0, acc[i2 * 2 + 1][0]);
                acc[i2 * 2 + 1][1] = ffma2(a1, b1, acc[i2 * 2 + 1][1]);
            }
        }
        if (s + 1 < S) {
            int nb = (s + 1) & 1;
            Asd[nb][akq + 0][arow] = make_float2(ra.x, ra.x);
            Asd[nb][akq + 1][arow] = make_float2(ra.y, ra.y);
            Asd[nb][akq + 2][arow] = make_float2(ra.z, ra.z);
            Asd[nb][akq + 3][arow] = make_float2(ra.w, ra.w);
            *(float4*)&Bs[nb][bkr][bcol] = rb;
            __syncthreads();
        }
    }

    // ---- epilogue ----
    float4 bb = *(const float4*)(bias + bn + cx * 4);
    if (EPI == 0 || EPI == 2) {
        #pragma unroll
        for (int i = 0; i < 16; ++i) {
            int r = bm + cy * 16 + i;
            float4 v;
            v.x = acc[i][0].x + bb.x; v.y = acc[i][0].y + bb.y;
            v.z = acc[i][1].x + bb.z; v.w = acc[i][1].y + bb.w;
            if (EPI == 2) {
                v.x = gelu_exact(v.x); v.y = gelu_exact(v.y);
                v.z = gelu_exact(v.z); v.w = gelu_exact(v.w);
            }
            *(float4*)(out + (size_t)r * N + bn + cx * 4) = v;
        }
    } else {
        float4 gg = *(const float4*)(lng + cx * 4);
        float4 be = *(const float4*)(lnb + cx * 4);
        #pragma unroll 4
        for (int i = 0; i < 16; ++i) {
            int r = bm + cy * 16 + i;
            float4 v;
            v.x = acc[i][0].x + bb.x; v.y = acc[i][0].y + bb.y;
            v.z = acc[i][1].x + bb.z; v.w = acc[i][1].y + bb.w;
            float s = wred(v.x + v.y + v.z + v.w);
            float m = s * (1.f / 128.f);
            float d0 = v.x - m, d1 = v.y - m, d2 = v.z - m, d3 = v.w - m;
            float vs = wred(d0 * d0 + d1 * d1 + d2 * d2 + d3 * d3);
            float inv = rsqrtf(vs * (1.f / 128.f) + 1e-3f);
            size_t rowoff;
            if (EPI == 3) {
                unsigned r_ = (unsigned)r;
                unsigned win = r_ / 49u, p = r_ - win * 49u;
                unsigned b = win >> 6, wloc = win & 63u, wr = wloc >> 3, wc = wloc & 7u;
                unsigned ii = p / 7u, jj = p - ii * 7u;
                unsigned sr = wr * 7 + ii + 3; if (sr >= 56) sr -= 56;
                unsigned sc = wc * 7 + jj + 3; if (sc >= 56) sc -= 56;
                rowoff = ((size_t)((b * 56 + sr) * 56 + sc)) * 128;
            } else {
                rowoff = (size_t)r * 128;
            }
            float4 xr = *(const float4*)(resid + rowoff + cx * 4);
            float4 o4;
            o4.x = xr.x + d0 * inv * gg.x + be.x;
            o4.y = xr.y + d1 * inv * gg.y + be.y;
            o4.z = xr.z + d2 * inv * gg.z + be.z;
            o4.w = xr.w + d3 * inv * gg.w + be.w;
            *(float4*)(out + rowoff + cx * 4) = o4;
        }
    }
}

// ---------------- K-core: per-window attention ----------------
#define SMEM_CORE_FLOATS (NTOK*QS + NTOK*KS + NTOK*CDIM + 4*NTOK*NTOK)

__global__ void __launch_bounds__(256, 2) k_core(const float* __restrict__ mask) {
    extern __shared__ float sm[];
    float* q  = sm;
    float* kk = q + NTOK * QS;
    float* v  = kk + NTOK * KS;
    float* at = v + NTOK * CDIM;
    __shared__ int pix[NTOK];

    int t = threadIdx.x;
    int win = blockIdx.x;
    int b = win >> 6, wloc = win & 63, wr = wloc >> 3, wc = wloc & 7;

    if (t < NTOK) {
        int i = t / WS, j = t % WS;
        int sr = (wr * WS + i + 3) % HW;
        int sc = (wc * WS + j + 3) % HW;
        pix[t] = (b * HW + sr) * HW + sc;
    }
    __syncthreads();

    for (int idx = t; idx < NTOK * 192; idx += 256) {
        int p = idx / 192, c2 = (idx % 192);
        float2 val = *(const float2*)(g_qkv + (size_t)pix[p] * 384 + c2 * 2);
        int c = c2 * 2;
        if (c < 128)       *(float2*)(q + p * QS + c) = val;
        else if (c < 256)  *(float2*)(kk + p * KS + (c - 128)) = val;
        else               *(float2*)(v + p * CDIM + (c - 256)) = val;
    }
    __syncthreads();

    for (int idx = t; idx < 392; idx += 256) {
        int isk = idx / 196, rem = idx % 196, h = rem / 49, p = rem % 49;
        float2* base = isk ? (float2*)(kk + p * KS + h * 32) : (float2*)(q + p * QS + h * 32);
        float2 s2 = make_float2(0.f, 0.f);
        #pragma unroll
        for (int d = 0; d < 16; ++d) s2 = ffma2(base[d], base[d], s2);
        float inv = rsqrtf(fmaxf(s2.x + s2.y, 1e-12f));
        #pragma unroll
        for (int d = 0; d < 16; ++d) { float2 vv = base[d]; vv.x *= inv; vv.y *= inv; base[d] = vv; }
    }
    __syncthreads();

    const float* mw = mask + (size_t)wloc * (NTOK * NTOK);
    for (int idx = t; idx < 4 * NTOK * NTOK; idx += 256) {
        int h = idx / 2401, rem = idx % 2401;
        int p = rem / 49, qq = rem % 49;
        const float2* qr = (const float2*)(q + p * QS + h * 32);
        const float2* kr = (const float2*)(kk + qq * KS + h * 32);
        float2 a0 = make_float2(0.f, 0.f), a1 = make_float2(0.f, 0.f);
        #pragma unroll
        for (int d = 0; d < 16; d += 2) {
            a0 = ffma2(qr[d], kr[d], a0);
            a1 = ffma2(qr[d + 1], kr[d + 1], a1);
        }
        float acc = a0.x + a0.y + a1.x + a1.y;
        int dy = p / WS - qq / WS + 6;
        int dx = p % WS - qq % WS + 6;
        at[idx] = fmaf(acc, g_scale[h], g_bias16[(dy * 13 + dx) * 4 + h] + mw[rem]);
    }
    __syncthreads();

    for (int idx = t; idx < 4 * NTOK; idx += 256) {
        float* row = at + idx * NTOK;
        float m = -1e30f;
        #pragma unroll 7
        for (int qq = 0; qq < NTOK; ++qq) m = fmaxf(m, row[qq]);
        float s = 0.f;
        #pragma unroll 7
        for (int qq = 0; qq < NTOK; ++qq) { float e = expf(row[qq] - m); row[qq] = e; s += e; }
        float inv = 1.f / s;
        #pragma unroll 7
        for (int qq = 0; qq < NTOK; ++qq) row[qq] *= inv;
    }
    __syncthreads();

    const float2* v2 = (const float2*)v;
    for (int idx = t; idx < NTOK * 64; idx += 256) {
        int p = idx >> 6, cp = idx & 63, h = cp >> 4;
        const float* ar = at + (h * 49 + p) * 49;
        float2 acc = make_float2(0.f, 0.f);
        #pragma unroll 7
        for (int qq = 0; qq < NTOK; ++qq) {
            float a = ar[qq];
            acc = ffma2(make_float2(a, a), v2[qq * 64 + cp], acc);
        }
        *(float2*)(g_o + ((size_t)win * NTOK + p) * 128 + cp * 2) = acc;
    }
}

// ---------------- launch ----------------
extern "C" void kernel_launch(void* const* d_in, const int* in_sizes, int n_in,
                              void* d_out, int out_size) {
    const float* x           = (const float*)d_in[0];
    const float* mask        = (const float*)d_in[1];
    const float* norm1_g     = (const float*)d_in[2];
    const float* norm1_b     = (const float*)d_in[3];
    const float* qkv_w       = (const float*)d_in[4];
    const float* q_bias      = (const float*)d_in[5];
    const float* v_bias      = (const float*)d_in[6];
    const float* logit_scale = (const float*)d_in[7];
    const float* rpe_w1      = (const float*)d_in[8];
    const float* rpe_b1      = (const float*)d_in[9];
    const float* rpe_w2      = (const float*)d_in[10];
    const float* proj_w      = (const float*)d_in[11];
    const float* proj_b      = (const float*)d_in[12];
    const float* norm2_g     = (const float*)d_in[13];
    const float* norm2_b     = (const float*)d_in[14];
    const float* fc1_w       = (const float*)d_in[15];
    const float* fc1_b       = (const float*)d_in[16];
    const float* fc2_w       = (const float*)d_in[17];
    const float* fc2_b       = (const float*)d_in[18];
    float* out = (float*)d_out;

    float *p_qkv, *p_o, *p_x1, *p_h, *p_qb;
    cudaGetSymbolAddress((void**)&p_qkv, g_qkv);
    cudaGetSymbolAddress((void**)&p_o,   g_o);
    cudaGetSymbolAddress((void**)&p_x1,  g_x1);
    cudaGetSymbolAddress((void**)&p_h,   g_h);
    cudaGetSymbolAddress((void**)&p_qb,  g_qkvbias);

    size_t smem_core = SMEM_CORE_FLOATS * sizeof(float);
    cudaFuncSetAttribute(k_core, cudaFuncAttributeMaxDynamicSharedMemorySize, (int)smem_core);

    k_prep<<<170, 128>>>(logit_scale, rpe_w1, rpe_b1, rpe_w2, q_bias, v_bias);

    dim3 gq(NPIX / 128, 3);
    k_gemm<128, 384, 0><<<gq, 256>>>(x, qkv_w, p_qb, p_qkv, nullptr, nullptr, nullptr);

    k_core<<<NWIN_TOT, 256, smem_core>>>(mask);

    dim3 gp(NPIX / 128, 1);
    k_gemm<128, 128, 3><<<gp, 256>>>(p_o, proj_w, proj_b, p_x1, x, norm1_g, norm1_b);

    dim3 g1(NPIX / 128, 4);
    k_gemm<128, 512, 2><<<g1, 256>>>(p_x1, fc1_w, fc1_b, p_h, nullptr, nullptr, nullptr);

    dim3 g2(NPIX / 128, 1);
    k_gemm<512, 128, 4><<<g2, 256>>>(p_h, fc2_w, fc2_b, out, p_x1, norm2_g, norm2_b);
}